// round 3
// baseline (speedup 1.0000x reference)
#include <cuda_runtime.h>
#include <math.h>

// ---------------- problem constants ----------------
#define Bsz   2
#define Tq    512
#define Dm    3584
#define NHh   28
#define KHh   4
#define Gh    7
#define Hd    128
#define SCc   3584
#define Stot  4096
#define Mrows 1024            // Bsz * Tq
#define QSCALE 0.08838834764831845f   // 1/sqrt(128)

// ---------------- device scratch ----------------
__device__ float g_q  [(size_t)Mrows * NHh * Hd];   // 14.7 MB
__device__ float g_enc[(size_t)Mrows * NHh * Hd];   // 14.7 MB
__device__ float g_cos[Mrows * 64];
__device__ float g_sin[Mrows * 64];

// ---------------- mRoPE cos/sin table ----------------
// positions: (3, B, T) int32. sections (16,24,24) over 64 freqs.
__global__ void rope_table_kernel(const int* __restrict__ positions) {
    int idx = blockIdx.x * blockDim.x + threadIdx.x;  // Mrows*64 = 65536
    if (idx >= Mrows * 64) return;
    int m = idx >> 6;
    int i = idx & 63;
    int j = (i < 16) ? 0 : ((i < 40) ? 1 : 2);
    int pos = positions[j * Mrows + m];
    double inv = pow(1.0e6, -(double)(2 * i) / 128.0);
    double ang = (double)pos * inv;
    const double TWO_PI = 6.283185307179586476925286766559;
    ang -= floor(ang / TWO_PI) * TWO_PI;
    float s, c;
    sincosf((float)ang, &s, &c);
    g_cos[idx] = c;
    g_sin[idx] = s;
}

// ---------------- fused QKV projection GEMM ----------------
// C[m, c] = sum_d x[m,d] * W[c/128][d, c%128], tiles 128x128x16.
// q -> g_q ; k,v -> cached output regions at s = SC + t.
__global__ __launch_bounds__(256) void gemm_qkv_kernel(
    const float* __restrict__ x,
    const float* __restrict__ wq, const float* __restrict__ wk,
    const float* __restrict__ wv,
    float* __restrict__ out_k, float* __restrict__ out_v)
{
    __shared__ __align__(16) float As[16][132];
    __shared__ __align__(16) float Bs[16][132];
    const int tid = threadIdx.x;
    const int bm  = blockIdx.x;
    const int c0  = blockIdx.y * 128;

    const float* W;
    int kind, head;
    if (c0 < NHh * Hd)              { kind = 0; head = c0 >> 7;                    W = wq + (size_t)head * Dm * Hd; }
    else if (c0 < (NHh + KHh) * Hd) { kind = 1; head = (c0 - NHh * Hd) >> 7;       W = wk + (size_t)head * Dm * Hd; }
    else                            { kind = 2; head = (c0 - (NHh + KHh) * Hd) >> 7; W = wv + (size_t)head * Dm * Hd; }

    const int ty = tid >> 4, tx = tid & 15;
    float acc[8][8];
    #pragma unroll
    for (int r = 0; r < 8; r++)
        #pragma unroll
        for (int c = 0; c < 8; c++) acc[r][c] = 0.f;

    const float* Abase = x + (size_t)(bm * 128) * Dm;

    for (int kt = 0; kt < Dm; kt += 16) {
        #pragma unroll
        for (int i = 0; i < 2; i++) {
            int f  = tid + 256 * i;
            int r  = f >> 2;
            int c4 = (f & 3) * 4;
            float4 v = *(const float4*)(Abase + (size_t)r * Dm + kt + c4);
            As[c4 + 0][r] = v.x; As[c4 + 1][r] = v.y;
            As[c4 + 2][r] = v.z; As[c4 + 3][r] = v.w;
        }
        #pragma unroll
        for (int i = 0; i < 2; i++) {
            int f  = tid + 256 * i;
            int d  = f >> 5;
            int c4 = (f & 31) * 4;
            *(float4*)&Bs[d][c4] = *(const float4*)(W + (size_t)(kt + d) * Hd + c4);
        }
        __syncthreads();
        #pragma unroll
        for (int kk = 0; kk < 16; kk++) {
            float4 t0 = *(const float4*)&As[kk][ty * 8];
            float4 t1 = *(const float4*)&As[kk][ty * 8 + 4];
            float4 u0 = *(const float4*)&Bs[kk][tx * 8];
            float4 u1 = *(const float4*)&Bs[kk][tx * 8 + 4];
            float a[8] = {t0.x, t0.y, t0.z, t0.w, t1.x, t1.y, t1.z, t1.w};
            float b[8] = {u0.x, u0.y, u0.z, u0.w, u1.x, u1.y, u1.z, u1.w};
            #pragma unroll
            for (int r = 0; r < 8; r++)
                #pragma unroll
                for (int c = 0; c < 8; c++)
                    acc[r][c] += a[r] * b[c];
        }
        __syncthreads();
    }

    #pragma unroll
    for (int r = 0; r < 8; r++) {
        int m = bm * 128 + ty * 8 + r;
        float4 v0 = make_float4(acc[r][0], acc[r][1], acc[r][2], acc[r][3]);
        float4 v1 = make_float4(acc[r][4], acc[r][5], acc[r][6], acc[r][7]);
        float* dst;
        if (kind == 0) {
            dst = g_q + (size_t)m * (NHh * Hd) + head * Hd + tx * 8;
        } else {
            int b = m >> 9, t = m & 511;
            size_t off = ((size_t)(b * Stot + SCc + t) * KHh + head) * Hd + tx * 8;
            dst = ((kind == 1) ? out_k : out_v) + off;
        }
        *(float4*)dst       = v0;
        *(float4*)(dst + 4) = v1;
    }
}

// ---------------- output projection GEMM ----------------
// out[m, d] = sum_c g_enc[m, c] * wo[c, d]; wo is row-major (3584, 3584).
__global__ __launch_bounds__(256) void gemm_out_kernel(
    const float* __restrict__ wo, float* __restrict__ outp)
{
    __shared__ __align__(16) float As[16][132];
    __shared__ __align__(16) float Bs[16][132];
    const int tid = threadIdx.x;
    const int bm  = blockIdx.x;
    const int c0  = blockIdx.y * 128;

    const int ty = tid >> 4, tx = tid & 15;
    float acc[8][8];
    #pragma unroll
    for (int r = 0; r < 8; r++)
        #pragma unroll
        for (int c = 0; c < 8; c++) acc[r][c] = 0.f;

    const float* Abase = g_enc + (size_t)(bm * 128) * Dm;

    for (int kt = 0; kt < Dm; kt += 16) {
        #pragma unroll
        for (int i = 0; i < 2; i++) {
            int f  = tid + 256 * i;
            int r  = f >> 2;
            int c4 = (f & 3) * 4;
            float4 v = *(const float4*)(Abase + (size_t)r * Dm + kt + c4);
            As[c4 + 0][r] = v.x; As[c4 + 1][r] = v.y;
            As[c4 + 2][r] = v.z; As[c4 + 3][r] = v.w;
        }
        #pragma unroll
        for (int i = 0; i < 2; i++) {
            int f  = tid + 256 * i;
            int d  = f >> 5;
            int c4 = (f & 31) * 4;
            *(float4*)&Bs[d][c4] = *(const float4*)(wo + (size_t)(kt + d) * Dm + c0 + c4);
        }
        __syncthreads();
        #pragma unroll
        for (int kk = 0; kk < 16; kk++) {
            float4 t0 = *(const float4*)&As[kk][ty * 8];
            float4 t1 = *(const float4*)&As[kk][ty * 8 + 4];
            float4 u0 = *(const float4*)&Bs[kk][tx * 8];
            float4 u1 = *(const float4*)&Bs[kk][tx * 8 + 4];
            float a[8] = {t0.x, t0.y, t0.z, t0.w, t1.x, t1.y, t1.z, t1.w};
            float b[8] = {u0.x, u0.y, u0.z, u0.w, u1.x, u1.y, u1.z, u1.w};
            #pragma unroll
            for (int r = 0; r < 8; r++)
                #pragma unroll
                for (int c = 0; c < 8; c++)
                    acc[r][c] += a[r] * b[c];
        }
        __syncthreads();
    }

    #pragma unroll
    for (int r = 0; r < 8; r++) {
        int m = bm * 128 + ty * 8 + r;
        float* dst = outp + (size_t)m * Dm + c0 + tx * 8;
        *(float4*)dst       = make_float4(acc[r][0], acc[r][1], acc[r][2], acc[r][3]);
        *(float4*)(dst + 4) = make_float4(acc[r][4], acc[r][5], acc[r][6], acc[r][7]);
    }
}

// ---------------- in-place RoPE ----------------
__global__ void rope_q_kernel() {
    int idx = blockIdx.x * blockDim.x + threadIdx.x;   // Mrows*NHh*64
    if (idx >= Mrows * NHh * 64) return;
    int m = idx / (NHh * 64);
    int r = idx - m * (NHh * 64);
    int n = r >> 6;
    int i = r & 63;
    float c = g_cos[m * 64 + i], s = g_sin[m * 64 + i];
    float* p = g_q + ((size_t)m * NHh + n) * Hd;
    float x1 = p[i], x2 = p[i + 64];
    p[i]      = (x1 * c - x2 * s) * QSCALE;
    p[i + 64] = (x2 * c + x1 * s) * QSCALE;
}

__global__ void rope_k_kernel(float* __restrict__ out_k) {
    int idx = blockIdx.x * blockDim.x + threadIdx.x;   // Mrows*KHh*64
    if (idx >= Mrows * KHh * 64) return;
    int m = idx / (KHh * 64);
    int r = idx - m * (KHh * 64);
    int kh = r >> 6;
    int i  = r & 63;
    int b = m >> 9, t = m & 511;
    float c = g_cos[m * 64 + i], s = g_sin[m * 64 + i];
    float* p = out_k + ((size_t)(b * Stot + SCc + t) * KHh + kh) * Hd;
    float x1 = p[i], x2 = p[i + 64];
    p[i]      = x1 * c - x2 * s;
    p[i + 64] = x2 * c + x1 * s;
}

// ---------------- flash attention ----------------
// grid: (T/64, G, B*K); 256 threads. smem: Qs^T[128][68], Ks^T[128][68],
// Vs[64][132], Ps^T[64][68] -> 120832 bytes (dynamic).
#define QS_STR 68
#define VS_STR 132
#define ATT_SMEM_FLOATS (128*68 + 128*68 + 64*132 + 64*68)
#define ATT_SMEM_BYTES  (ATT_SMEM_FLOATS * 4)

__global__ __launch_bounds__(256) void attn_kernel(
    const float* __restrict__ kc, const float* __restrict__ vc)
{
    extern __shared__ __align__(16) float sm[];
    float* Qs = sm;
    float* Ks = Qs + 128 * QS_STR;
    float* Vs = Ks + 128 * QS_STR;
    float* Ps = Vs + 64 * VS_STR;

    const int tid = threadIdx.x;
    const int qt  = blockIdx.x;        // q tile
    const int g   = blockIdx.y;        // head within group
    const int bk  = blockIdx.z;
    const int b   = bk >> 2, kh = bk & 3;
    const int n   = kh * Gh + g;
    const int t0  = qt * 64;

    // load Q transposed: Qs[h][r]
    size_t qbase = ((size_t)(b * Tq + t0) * NHh + n) * Hd;
    for (int f = tid; f < 64 * 32; f += 256) {
        int r  = f >> 5;
        int c4 = (f & 31) * 4;
        float4 v = *(const float4*)(g_q + qbase + (size_t)r * (NHh * Hd) + c4);
        Qs[(c4 + 0) * QS_STR + r] = v.x;
        Qs[(c4 + 1) * QS_STR + r] = v.y;
        Qs[(c4 + 2) * QS_STR + r] = v.z;
        Qs[(c4 + 3) * QS_STR + r] = v.w;
    }

    const int tm = tid >> 4, tn = tid & 15;
    float o[4][8];
    #pragma unroll
    for (int r = 0; r < 4; r++)
        #pragma unroll
        for (int c = 0; c < 8; c++) o[r][c] = 0.f;
    float mrun[4] = {-1e30f, -1e30f, -1e30f, -1e30f};
    float lrun[4] = {0.f, 0.f, 0.f, 0.f};

    size_t kvbase = ((size_t)b * Stot * KHh + kh) * Hd;
    const int ntiles = (SCc + t0 + 64) >> 6;

    for (int it = 0; it < ntiles; it++) {
        int s0 = it * 64;
        __syncthreads();  // prior PV done with Ks/Vs/Ps
        // load K^T and V
        for (int f = tid; f < 64 * 32; f += 256) {
            int c  = f >> 5;
            int c4 = (f & 31) * 4;
            size_t addr = kvbase + (size_t)(s0 + c) * (KHh * Hd) + c4;
            float4 kv = *(const float4*)(kc + addr);
            Ks[(c4 + 0) * QS_STR + c] = kv.x;
            Ks[(c4 + 1) * QS_STR + c] = kv.y;
            Ks[(c4 + 2) * QS_STR + c] = kv.z;
            Ks[(c4 + 3) * QS_STR + c] = kv.w;
            *(float4*)&Vs[c * VS_STR + c4] = *(const float4*)(vc + addr);
        }
        __syncthreads();

        // scores: 4x4 per thread over 128 dims
        float sc[4][4];
        #pragma unroll
        for (int r = 0; r < 4; r++)
            #pragma unroll
            for (int c = 0; c < 4; c++) sc[r][c] = 0.f;
        #pragma unroll 8
        for (int kk = 0; kk < 128; kk++) {
            float4 qv = *(const float4*)&Qs[kk * QS_STR + tm * 4];
            float4 kv = *(const float4*)&Ks[kk * QS_STR + tn * 4];
            float qa[4] = {qv.x, qv.y, qv.z, qv.w};
            float ka[4] = {kv.x, kv.y, kv.z, kv.w};
            #pragma unroll
            for (int r = 0; r < 4; r++)
                #pragma unroll
                for (int c = 0; c < 4; c++)
                    sc[r][c] += qa[r] * ka[c];
        }

        // causal mask (matches reference mask: allowed iff s <= SC + t)
        if (s0 + 63 > SCc + t0) {
            #pragma unroll
            for (int r = 0; r < 4; r++)
                #pragma unroll
                for (int c = 0; c < 4; c++)
                    if (s0 + tn * 4 + c > SCc + t0 + tm * 4 + r)
                        sc[r][c] = -1e30f;
        }

        // online softmax
        #pragma unroll
        for (int ri = 0; ri < 4; ri++) {
            float mloc = fmaxf(fmaxf(sc[ri][0], sc[ri][1]), fmaxf(sc[ri][2], sc[ri][3]));
            #pragma unroll
            for (int off = 8; off > 0; off >>= 1)
                mloc = fmaxf(mloc, __shfl_xor_sync(0xffffffffu, mloc, off));
            float mnew = fmaxf(mrun[ri], mloc);
            float corr = __expf(mrun[ri] - mnew);
            float rs = 0.f;
            #pragma unroll
            for (int cj = 0; cj < 4; cj++) {
                float p = __expf(sc[ri][cj] - mnew);
                rs += p;
                Ps[(tn * 4 + cj) * QS_STR + tm * 4 + ri] = p;
            }
            #pragma unroll
            for (int off = 8; off > 0; off >>= 1)
                rs += __shfl_xor_sync(0xffffffffu, rs, off);
            lrun[ri] = lrun[ri] * corr + rs;
            mrun[ri] = mnew;
            #pragma unroll
            for (int j = 0; j < 8; j++) o[ri][j] *= corr;
        }
        __syncthreads();

        // O += P @ V (4 rows x 8 h-cols per thread)
        #pragma unroll 4
        for (int c = 0; c < 64; c++) {
            float4 pv = *(const float4*)&Ps[c * QS_STR + tm * 4];
            float4 v0 = *(const float4*)&Vs[c * VS_STR + tn * 8];
            float4 v1 = *(const float4*)&Vs[c * VS_STR + tn * 8 + 4];
            float pa[4] = {pv.x, pv.y, pv.z, pv.w};
            float va[8] = {v0.x, v0.y, v0.z, v0.w, v1.x, v1.y, v1.z, v1.w};
            #pragma unroll
            for (int r = 0; r < 4; r++)
                #pragma unroll
                for (int j = 0; j < 8; j++)
                    o[r][j] += pa[r] * va[j];
        }
    }

    // epilogue
    #pragma unroll
    for (int ri = 0; ri < 4; ri++) {
        float inv = 1.0f / lrun[ri];
        int t = t0 + tm * 4 + ri;
        size_t dst = ((size_t)(b * Tq + t) * NHh + n) * Hd + tn * 8;
        *(float4*)(g_enc + dst)     = make_float4(o[ri][0]*inv, o[ri][1]*inv, o[ri][2]*inv, o[ri][3]*inv);
        *(float4*)(g_enc + dst + 4) = make_float4(o[ri][4]*inv, o[ri][5]*inv, o[ri][6]*inv, o[ri][7]*inv);
    }
}

// ---------------- launch ----------------
extern "C" void kernel_launch(void* const* d_in, const int* in_sizes, int n_in,
                              void* d_out, int out_size) {
    (void)in_sizes; (void)n_in; (void)out_size;
    const float* x         = (const float*)d_in[0];
    const int*   positions = (const int*)  d_in[1];
    // d_in[2] = attn_mask (structural: full cache + causal) — applied analytically
    const float* cache_k   = (const float*)d_in[3];
    const float* cache_v   = (const float*)d_in[4];
    const float* wq        = (const float*)d_in[5];
    const float* wk        = (const float*)d_in[6];
    const float* wv        = (const float*)d_in[7];
    const float* wo        = (const float*)d_in[8];

    float* outp  = (float*)d_out;
    float* out_k = outp  + (size_t)Mrows * Dm;               // cached_k (B,S,K,H)
    float* out_v = out_k + (size_t)Bsz * Stot * KHh * Hd;    // cached_v (B,S,K,H)

    // 1. copy existing cache into output (contiguous per batch: s < SC)
    const size_t per_b = (size_t)SCc * KHh * Hd;             // floats
    for (int b = 0; b < Bsz; b++) {
        cudaMemcpyAsync(out_k + (size_t)b * Stot * KHh * Hd,
                        cache_k + (size_t)b * per_b,
                        per_b * sizeof(float), cudaMemcpyDeviceToDevice, 0);
        cudaMemcpyAsync(out_v + (size_t)b * Stot * KHh * Hd,
                        cache_v + (size_t)b * per_b,
                        per_b * sizeof(float), cudaMemcpyDeviceToDevice, 0);
    }

    // 2. RoPE cos/sin table
    rope_table_kernel<<<(Mrows * 64) / 256, 256>>>(positions);

    // 3. fused QKV projection
    dim3 gq(Mrows / 128, (NHh + 2 * KHh));   // 8 x 36
    gemm_qkv_kernel<<<gq, 256>>>(x, wq, wk, wv, out_k, out_v);

    // 4. RoPE (in-place)
    rope_q_kernel<<<(Mrows * NHh * 64) / 256, 256>>>();
    rope_k_kernel<<<(Mrows * KHh * 64) / 256, 256>>>(out_k);

    // 5. flash attention
    cudaFuncSetAttribute(attn_kernel, cudaFuncAttributeMaxDynamicSharedMemorySize,
                         ATT_SMEM_BYTES);
    dim3 ga(Tq / 64, Gh, Bsz * KHh);         // 8 x 7 x 8
    attn_kernel<<<ga, 256, ATT_SMEM_BYTES>>>(out_k, out_v);

    // 6. output projection
    dim3 go(Mrows / 128, Dm / 128);          // 8 x 28
    gemm_out_kernel<<<go, 256>>>(wo, outp);
}

// round 4
// speedup vs baseline: 1.0001x; 1.0001x over previous
#include <cuda_runtime.h>
#include <math.h>

// ---------------- problem constants ----------------
#define Bsz   2
#define Tq    512
#define Dm    3584
#define NHh   28
#define KHh   4
#define Gh    7
#define Hd    128
#define SCc   3584
#define Stot  4096
#define Mrows 1024            // Bsz * Tq
#define QSCALE 0.08838834764831845f   // 1/sqrt(128)

// ---------------- device scratch ----------------
__device__ float g_q  [(size_t)Mrows * NHh * Hd];   // 14.7 MB
__device__ float g_enc[(size_t)Mrows * NHh * Hd];   // 14.7 MB
__device__ float g_cos[Mrows * 64];
__device__ float g_sin[Mrows * 64];

// ---------------- mRoPE cos/sin table ----------------
// positions: (3, B, T) int32. sections (16,24,24) over 64 freqs.
__global__ void rope_table_kernel(const int* __restrict__ positions) {
    int idx = blockIdx.x * blockDim.x + threadIdx.x;  // Mrows*64 = 65536
    if (idx >= Mrows * 64) return;
    int m = idx >> 6;
    int i = idx & 63;
    int j = (i < 16) ? 0 : ((i < 40) ? 1 : 2);
    int pos = positions[j * Mrows + m];
    double inv = pow(1.0e6, -(double)(2 * i) / 128.0);
    double ang = (double)pos * inv;
    const double TWO_PI = 6.283185307179586476925286766559;
    ang -= floor(ang / TWO_PI) * TWO_PI;
    float s, c;
    sincosf((float)ang, &s, &c);
    g_cos[idx] = c;
    g_sin[idx] = s;
}

// ---------------- fused QKV projection GEMM ----------------
// C[m, c] = sum_d x[m,d] * W[c/128][d, c%128], tiles 128x128x16.
// q -> g_q ; k,v -> cached output regions at s = SC + t.
__global__ __launch_bounds__(256) void gemm_qkv_kernel(
    const float* __restrict__ x,
    const float* __restrict__ wq, const float* __restrict__ wk,
    const float* __restrict__ wv,
    float* __restrict__ out_k, float* __restrict__ out_v)
{
    __shared__ __align__(16) float As[16][132];
    __shared__ __align__(16) float Bs[16][132];
    const int tid = threadIdx.x;
    const int bm  = blockIdx.x;
    const int c0  = blockIdx.y * 128;

    const float* W;
    int kind, head;
    if (c0 < NHh * Hd)              { kind = 0; head = c0 >> 7;                    W = wq + (size_t)head * Dm * Hd; }
    else if (c0 < (NHh + KHh) * Hd) { kind = 1; head = (c0 - NHh * Hd) >> 7;       W = wk + (size_t)head * Dm * Hd; }
    else                            { kind = 2; head = (c0 - (NHh + KHh) * Hd) >> 7; W = wv + (size_t)head * Dm * Hd; }

    const int ty = tid >> 4, tx = tid & 15;
    float acc[8][8];
    #pragma unroll
    for (int r = 0; r < 8; r++)
        #pragma unroll
        for (int c = 0; c < 8; c++) acc[r][c] = 0.f;

    const float* Abase = x + (size_t)(bm * 128) * Dm;

    for (int kt = 0; kt < Dm; kt += 16) {
        #pragma unroll
        for (int i = 0; i < 2; i++) {
            int f  = tid + 256 * i;
            int r  = f >> 2;
            int c4 = (f & 3) * 4;
            float4 v = *(const float4*)(Abase + (size_t)r * Dm + kt + c4);
            As[c4 + 0][r] = v.x; As[c4 + 1][r] = v.y;
            As[c4 + 2][r] = v.z; As[c4 + 3][r] = v.w;
        }
        #pragma unroll
        for (int i = 0; i < 2; i++) {
            int f  = tid + 256 * i;
            int d  = f >> 5;
            int c4 = (f & 31) * 4;
            *(float4*)&Bs[d][c4] = *(const float4*)(W + (size_t)(kt + d) * Hd + c4);
        }
        __syncthreads();
        #pragma unroll
        for (int kk = 0; kk < 16; kk++) {
            float4 t0 = *(const float4*)&As[kk][ty * 8];
            float4 t1 = *(const float4*)&As[kk][ty * 8 + 4];
            float4 u0 = *(const float4*)&Bs[kk][tx * 8];
            float4 u1 = *(const float4*)&Bs[kk][tx * 8 + 4];
            float a[8] = {t0.x, t0.y, t0.z, t0.w, t1.x, t1.y, t1.z, t1.w};
            float b[8] = {u0.x, u0.y, u0.z, u0.w, u1.x, u1.y, u1.z, u1.w};
            #pragma unroll
            for (int r = 0; r < 8; r++)
                #pragma unroll
                for (int c = 0; c < 8; c++)
                    acc[r][c] += a[r] * b[c];
        }
        __syncthreads();
    }

    #pragma unroll
    for (int r = 0; r < 8; r++) {
        int m = bm * 128 + ty * 8 + r;
        float4 v0 = make_float4(acc[r][0], acc[r][1], acc[r][2], acc[r][3]);
        float4 v1 = make_float4(acc[r][4], acc[r][5], acc[r][6], acc[r][7]);
        float* dst;
        if (kind == 0) {
            dst = g_q + (size_t)m * (NHh * Hd) + head * Hd + tx * 8;
        } else {
            int b = m >> 9, t = m & 511;
            size_t off = ((size_t)(b * Stot + SCc + t) * KHh + head) * Hd + tx * 8;
            dst = ((kind == 1) ? out_k : out_v) + off;
        }
        *(float4*)dst       = v0;
        *(float4*)(dst + 4) = v1;
    }
}

// ---------------- output projection GEMM ----------------
// out[m, d] = sum_c g_enc[m, c] * wo[c, d]; wo is row-major (3584, 3584).
__global__ __launch_bounds__(256) void gemm_out_kernel(
    const float* __restrict__ wo, float* __restrict__ outp)
{
    __shared__ __align__(16) float As[16][132];
    __shared__ __align__(16) float Bs[16][132];
    const int tid = threadIdx.x;
    const int bm  = blockIdx.x;
    const int c0  = blockIdx.y * 128;

    const int ty = tid >> 4, tx = tid & 15;
    float acc[8][8];
    #pragma unroll
    for (int r = 0; r < 8; r++)
        #pragma unroll
        for (int c = 0; c < 8; c++) acc[r][c] = 0.f;

    const float* Abase = g_enc + (size_t)(bm * 128) * Dm;

    for (int kt = 0; kt < Dm; kt += 16) {
        #pragma unroll
        for (int i = 0; i < 2; i++) {
            int f  = tid + 256 * i;
            int r  = f >> 2;
            int c4 = (f & 3) * 4;
            float4 v = *(const float4*)(Abase + (size_t)r * Dm + kt + c4);
            As[c4 + 0][r] = v.x; As[c4 + 1][r] = v.y;
            As[c4 + 2][r] = v.z; As[c4 + 3][r] = v.w;
        }
        #pragma unroll
        for (int i = 0; i < 2; i++) {
            int f  = tid + 256 * i;
            int d  = f >> 5;
            int c4 = (f & 31) * 4;
            *(float4*)&Bs[d][c4] = *(const float4*)(wo + (size_t)(kt + d) * Dm + c0 + c4);
        }
        __syncthreads();
        #pragma unroll
        for (int kk = 0; kk < 16; kk++) {
            float4 t0 = *(const float4*)&As[kk][ty * 8];
            float4 t1 = *(const float4*)&As[kk][ty * 8 + 4];
            float4 u0 = *(const float4*)&Bs[kk][tx * 8];
            float4 u1 = *(const float4*)&Bs[kk][tx * 8 + 4];
            float a[8] = {t0.x, t0.y, t0.z, t0.w, t1.x, t1.y, t1.z, t1.w};
            float b[8] = {u0.x, u0.y, u0.z, u0.w, u1.x, u1.y, u1.z, u1.w};
            #pragma unroll
            for (int r = 0; r < 8; r++)
                #pragma unroll
                for (int c = 0; c < 8; c++)
                    acc[r][c] += a[r] * b[c];
        }
        __syncthreads();
    }

    #pragma unroll
    for (int r = 0; r < 8; r++) {
        int m = bm * 128 + ty * 8 + r;
        float* dst = outp + (size_t)m * Dm + c0 + tx * 8;
        *(float4*)dst       = make_float4(acc[r][0], acc[r][1], acc[r][2], acc[r][3]);
        *(float4*)(dst + 4) = make_float4(acc[r][4], acc[r][5], acc[r][6], acc[r][7]);
    }
}

// ---------------- in-place RoPE ----------------
__global__ void rope_q_kernel() {
    int idx = blockIdx.x * blockDim.x + threadIdx.x;   // Mrows*NHh*64
    if (idx >= Mrows * NHh * 64) return;
    int m = idx / (NHh * 64);
    int r = idx - m * (NHh * 64);
    int n = r >> 6;
    int i = r & 63;
    float c = g_cos[m * 64 + i], s = g_sin[m * 64 + i];
    float* p = g_q + ((size_t)m * NHh + n) * Hd;
    float x1 = p[i], x2 = p[i + 64];
    p[i]      = (x1 * c - x2 * s) * QSCALE;
    p[i + 64] = (x2 * c + x1 * s) * QSCALE;
}

__global__ void rope_k_kernel(float* __restrict__ out_k) {
    int idx = blockIdx.x * blockDim.x + threadIdx.x;   // Mrows*KHh*64
    if (idx >= Mrows * KHh * 64) return;
    int m = idx / (KHh * 64);
    int r = idx - m * (KHh * 64);
    int kh = r >> 6;
    int i  = r & 63;
    int b = m >> 9, t = m & 511;
    float c = g_cos[m * 64 + i], s = g_sin[m * 64 + i];
    float* p = out_k + ((size_t)(b * Stot + SCc + t) * KHh + kh) * Hd;
    float x1 = p[i], x2 = p[i + 64];
    p[i]      = x1 * c - x2 * s;
    p[i + 64] = x2 * c + x1 * s;
}

// ---------------- flash attention ----------------
// grid: (T/64, G, B*K); 256 threads. smem: Qs^T[128][68], Ks^T[128][68],
// Vs[64][132], Ps^T[64][68] -> 120832 bytes (dynamic).
#define QS_STR 68
#define VS_STR 132
#define ATT_SMEM_FLOATS (128*68 + 128*68 + 64*132 + 64*68)
#define ATT_SMEM_BYTES  (ATT_SMEM_FLOATS * 4)

__global__ __launch_bounds__(256) void attn_kernel(
    const float* __restrict__ kc, const float* __restrict__ vc)
{
    extern __shared__ __align__(16) float sm[];
    float* Qs = sm;
    float* Ks = Qs + 128 * QS_STR;
    float* Vs = Ks + 128 * QS_STR;
    float* Ps = Vs + 64 * VS_STR;

    const int tid = threadIdx.x;
    const int qt  = blockIdx.x;        // q tile
    const int g   = blockIdx.y;        // head within group
    const int bk  = blockIdx.z;
    const int b   = bk >> 2, kh = bk & 3;
    const int n   = kh * Gh + g;
    const int t0  = qt * 64;

    // load Q transposed: Qs[h][r]
    size_t qbase = ((size_t)(b * Tq + t0) * NHh + n) * Hd;
    for (int f = tid; f < 64 * 32; f += 256) {
        int r  = f >> 5;
        int c4 = (f & 31) * 4;
        float4 v = *(const float4*)(g_q + qbase + (size_t)r * (NHh * Hd) + c4);
        Qs[(c4 + 0) * QS_STR + r] = v.x;
        Qs[(c4 + 1) * QS_STR + r] = v.y;
        Qs[(c4 + 2) * QS_STR + r] = v.z;
        Qs[(c4 + 3) * QS_STR + r] = v.w;
    }

    const int tm = tid >> 4, tn = tid & 15;
    float o[4][8];
    #pragma unroll
    for (int r = 0; r < 4; r++)
        #pragma unroll
        for (int c = 0; c < 8; c++) o[r][c] = 0.f;
    float mrun[4] = {-1e30f, -1e30f, -1e30f, -1e30f};
    float lrun[4] = {0.f, 0.f, 0.f, 0.f};

    size_t kvbase = ((size_t)b * Stot * KHh + kh) * Hd;
    const int ntiles = (SCc + t0 + 64) >> 6;

    for (int it = 0; it < ntiles; it++) {
        int s0 = it * 64;
        __syncthreads();  // prior PV done with Ks/Vs/Ps
        // load K^T and V
        for (int f = tid; f < 64 * 32; f += 256) {
            int c  = f >> 5;
            int c4 = (f & 31) * 4;
            size_t addr = kvbase + (size_t)(s0 + c) * (KHh * Hd) + c4;
            float4 kv = *(const float4*)(kc + addr);
            Ks[(c4 + 0) * QS_STR + c] = kv.x;
            Ks[(c4 + 1) * QS_STR + c] = kv.y;
            Ks[(c4 + 2) * QS_STR + c] = kv.z;
            Ks[(c4 + 3) * QS_STR + c] = kv.w;
            *(float4*)&Vs[c * VS_STR + c4] = *(const float4*)(vc + addr);
        }
        __syncthreads();

        // scores: 4x4 per thread over 128 dims
        float sc[4][4];
        #pragma unroll
        for (int r = 0; r < 4; r++)
            #pragma unroll
            for (int c = 0; c < 4; c++) sc[r][c] = 0.f;
        #pragma unroll 8
        for (int kk = 0; kk < 128; kk++) {
            float4 qv = *(const float4*)&Qs[kk * QS_STR + tm * 4];
            float4 kv = *(const float4*)&Ks[kk * QS_STR + tn * 4];
            float qa[4] = {qv.x, qv.y, qv.z, qv.w};
            float ka[4] = {kv.x, kv.y, kv.z, kv.w};
            #pragma unroll
            for (int r = 0; r < 4; r++)
                #pragma unroll
                for (int c = 0; c < 4; c++)
                    sc[r][c] += qa[r] * ka[c];
        }

        // causal mask (matches reference mask: allowed iff s <= SC + t)
        if (s0 + 63 > SCc + t0) {
            #pragma unroll
            for (int r = 0; r < 4; r++)
                #pragma unroll
                for (int c = 0; c < 4; c++)
                    if (s0 + tn * 4 + c > SCc + t0 + tm * 4 + r)
                        sc[r][c] = -1e30f;
        }

        // online softmax
        #pragma unroll
        for (int ri = 0; ri < 4; ri++) {
            float mloc = fmaxf(fmaxf(sc[ri][0], sc[ri][1]), fmaxf(sc[ri][2], sc[ri][3]));
            #pragma unroll
            for (int off = 8; off > 0; off >>= 1)
                mloc = fmaxf(mloc, __shfl_xor_sync(0xffffffffu, mloc, off));
            float mnew = fmaxf(mrun[ri], mloc);
            float corr = __expf(mrun[ri] - mnew);
            float rs = 0.f;
            #pragma unroll
            for (int cj = 0; cj < 4; cj++) {
                float p = __expf(sc[ri][cj] - mnew);
                rs += p;
                Ps[(tn * 4 + cj) * QS_STR + tm * 4 + ri] = p;
            }
            #pragma unroll
            for (int off = 8; off > 0; off >>= 1)
                rs += __shfl_xor_sync(0xffffffffu, rs, off);
            lrun[ri] = lrun[ri] * corr + rs;
            mrun[ri] = mnew;
            #pragma unroll
            for (int j = 0; j < 8; j++) o[ri][j] *= corr;
        }
        __syncthreads();

        // O += P @ V (4 rows x 8 h-cols per thread)
        #pragma unroll 4
        for (int c = 0; c < 64; c++) {
            float4 pv = *(const float4*)&Ps[c * QS_STR + tm * 4];
            float4 v0 = *(const float4*)&Vs[c * VS_STR + tn * 8];
            float4 v1 = *(const float4*)&Vs[c * VS_STR + tn * 8 + 4];
            float pa[4] = {pv.x, pv.y, pv.z, pv.w};
            float va[8] = {v0.x, v0.y, v0.z, v0.w, v1.x, v1.y, v1.z, v1.w};
            #pragma unroll
            for (int r = 0; r < 4; r++)
                #pragma unroll
                for (int j = 0; j < 8; j++)
                    o[r][j] += pa[r] * va[j];
        }
    }

    // epilogue
    #pragma unroll
    for (int ri = 0; ri < 4; ri++) {
        float inv = 1.0f / lrun[ri];
        int t = t0 + tm * 4 + ri;
        size_t dst = ((size_t)(b * Tq + t) * NHh + n) * Hd + tn * 8;
        *(float4*)(g_enc + dst)     = make_float4(o[ri][0]*inv, o[ri][1]*inv, o[ri][2]*inv, o[ri][3]*inv);
        *(float4*)(g_enc + dst + 4) = make_float4(o[ri][4]*inv, o[ri][5]*inv, o[ri][6]*inv, o[ri][7]*inv);
    }
}

// ---------------- launch ----------------
extern "C" void kernel_launch(void* const* d_in, const int* in_sizes, int n_in,
                              void* d_out, int out_size) {
    (void)in_sizes; (void)n_in; (void)out_size;
    const float* x         = (const float*)d_in[0];
    const int*   positions = (const int*)  d_in[1];
    // d_in[2] = attn_mask (structural: full cache + causal) — applied analytically
    const float* cache_k   = (const float*)d_in[3];
    const float* cache_v   = (const float*)d_in[4];
    const float* wq        = (const float*)d_in[5];
    const float* wk        = (const float*)d_in[6];
    const float* wv        = (const float*)d_in[7];
    const float* wo        = (const float*)d_in[8];

    float* outp  = (float*)d_out;
    float* out_k = outp  + (size_t)Mrows * Dm;               // cached_k (B,S,K,H)
    float* out_v = out_k + (size_t)Bsz * Stot * KHh * Hd;    // cached_v (B,S,K,H)

    // 1. copy existing cache into output (contiguous per batch: s < SC)
    const size_t per_b = (size_t)SCc * KHh * Hd;             // floats
    for (int b = 0; b < Bsz; b++) {
        cudaMemcpyAsync(out_k + (size_t)b * Stot * KHh * Hd,
                        cache_k + (size_t)b * per_b,
                        per_b * sizeof(float), cudaMemcpyDeviceToDevice, 0);
        cudaMemcpyAsync(out_v + (size_t)b * Stot * KHh * Hd,
                        cache_v + (size_t)b * per_b,
                        per_b * sizeof(float), cudaMemcpyDeviceToDevice, 0);
    }

    // 2. RoPE cos/sin table
    rope_table_kernel<<<(Mrows * 64) / 256, 256>>>(positions);

    // 3. fused QKV projection
    dim3 gq(Mrows / 128, (NHh + 2 * KHh));   // 8 x 36
    gemm_qkv_kernel<<<gq, 256>>>(x, wq, wk, wv, out_k, out_v);

    // 4. RoPE (in-place)
    rope_q_kernel<<<(Mrows * NHh * 64) / 256, 256>>>();
    rope_k_kernel<<<(Mrows * KHh * 64) / 256, 256>>>(out_k);

    // 5. flash attention
    cudaFuncSetAttribute(attn_kernel, cudaFuncAttributeMaxDynamicSharedMemorySize,
                         ATT_SMEM_BYTES);
    dim3 ga(Tq / 64, Gh, Bsz * KHh);         // 8 x 7 x 8
    attn_kernel<<<ga, 256, ATT_SMEM_BYTES>>>(out_k, out_v);

    // 6. output projection
    dim3 go(Mrows / 128, Dm / 128);          // 8 x 28
    gemm_out_kernel<<<go, 256>>>(wo, outp);
}